// round 7
// baseline (speedup 1.0000x reference)
#include <cuda_runtime.h>
#include <cuda_bf16.h>
#include <cuda_fp16.h>
#include <cstdint>
#include <cstddef>

// Problem constants
#define NB   4
#define NTQ  256
#define NTK  256
#define ND   1024
#define NA   512

#define GRID_SCORE 148     // persistent: 1 CTA per SM

// Scratch (allocation-free rule: __device__ globals). Projections stored in
// half precision, pre-packed for the score kernel.
__device__ __half2 g_qph[NB * NTQ * (NA / 2)];   // [b*TQ+q][a/2]
__device__ __half2 g_kph[(NA / 2) * NB * NTK];   // [a/2][b*TK+t]

// ---------------------------------------------------------------------------
// Helpers
// ---------------------------------------------------------------------------
__device__ __forceinline__ uint32_t cvta_shared_u32(const void* p) {
    uint32_t a;
    asm("{ .reg .u64 t; cvta.to.shared.u64 t, %1; cvt.u32.u64 %0, t; }"
        : "=r"(a) : "l"(p));
    return a;
}

// Pack two floats into bf16x2 (a -> low 16 bits, b -> high).
__device__ __forceinline__ uint32_t pack_bf16x2(float a, float b) {
    uint32_t r;
    asm("cvt.rn.bf16x2.f32 %0, %1, %2;" : "=r"(r) : "f"(b), "f"(a));
    return r;
}

__device__ __forceinline__ void ldsm_x4(uint32_t* r, uint32_t addr) {
    asm volatile("ldmatrix.sync.aligned.m8n8.x4.shared.b16 {%0,%1,%2,%3}, [%4];"
                 : "=r"(r[0]), "=r"(r[1]), "=r"(r[2]), "=r"(r[3]) : "r"(addr));
}

__device__ __forceinline__ void mma_bf16(float* c, const uint32_t* a, const uint32_t* b) {
    asm volatile(
        "mma.sync.aligned.m16n8k16.row.col.f32.bf16.bf16.f32 "
        "{%0,%1,%2,%3}, {%4,%5,%6,%7}, {%8,%9}, {%0,%1,%2,%3};"
        : "+f"(c[0]), "+f"(c[1]), "+f"(c[2]), "+f"(c[3])
        : "r"(a[0]), "r"(a[1]), "r"(a[2]), "r"(a[3]), "r"(b[0]), "r"(b[1]));
}

__device__ __forceinline__ __half2 tanh_h2(__half2 x) {
    uint32_t xi = *(uint32_t*)&x, r;
    asm("tanh.approx.f16x2 %0, %1;" : "=r"(r) : "r"(xi));
    return *(__half2*)&r;
}

// ---------------------------------------------------------------------------
// Tensor-core projection GEMM via mma.sync bf16 hi/lo split (3-MMA fp32 emu).
// Y[m][n] = sum_d X[m][d] * W[n][d];  M=1024 per z, N=512, K=1024.
// CTA tile 128(m) x 64(n), K-chunk 64, 8 warps (4m x 2n, 32x32 each).
// z=0: Q*W1 -> g_qph (row-major, half2-packed over a).
// z=1: K*W2 -> g_kph (transposed [a/2][m], half2-packed over a).
// ---------------------------------------------------------------------------
#define BM 128
#define BN 64
#define BK 64
#define RS 72                    // smem row stride in bf16 (144 B)
#define A_TILE_B  (BM * RS * 2)  // 18432
#define B_TILE_B  (BN * RS * 2)  //  9216
#define STAGE_B   (2 * A_TILE_B + 2 * B_TILE_B)   // Ah, Al, Bh, Bl = 55296
#define OFF_AH 0
#define OFF_AL A_TILE_B
#define OFF_BH (2 * A_TILE_B)
#define OFF_BL (2 * A_TILE_B + B_TILE_B)
#define SMEM_DYN (2 * STAGE_B)   // 110592

extern __shared__ char dynsmem[];

__global__ __launch_bounds__(256, 1) void proj_tc_kernel(
    const float* __restrict__ Qin, const float* __restrict__ Kin,
    const float* __restrict__ W1,  const float* __restrict__ W2)
{
    const int z  = blockIdx.z;
    const float* X = z ? Kin : Qin;
    const float* W = z ? W2  : W1;
    const int m0 = blockIdx.y * BM;
    const int n0 = blockIdx.x * BN;

    const int tid  = threadIdx.x;
    const int wid  = tid >> 5;
    const int lane = tid & 31;
    const int wm   = wid >> 1;        // 0..3
    const int wn   = wid & 1;         // 0..1

    const uint32_t sbase = cvta_shared_u32(dynsmem);

    const int a_row = (lane & 7) + ((lane >> 3) & 1) * 8;   // 0..15
    const int a_kof = (lane >> 4) * 8;                      // 0 / 8
    const int b_row = (lane & 7) + ((lane >> 4) & 1) * 8;
    const int b_kof = ((lane >> 3) & 1) * 8;

    float acc[2][4][4] = {};   // [mi][nf][4]

    float4 va[8], vb[4];

    auto load_regs = [&](int ch) {
        const int k0 = ch * BK;
        #pragma unroll
        for (int i = 0; i < 8; i++) {
            const int idx = tid + i * 256;
            const int row = idx >> 4;
            const int c4  = (idx & 15) * 4;
            va[i] = *(const float4*)(X + (size_t)(m0 + row) * ND + k0 + c4);
        }
        #pragma unroll
        for (int i = 0; i < 4; i++) {
            const int idx = tid + i * 256;
            const int row = idx >> 4;
            const int c4  = (idx & 15) * 4;
            vb[i] = *(const float4*)(W + (size_t)(n0 + row) * ND + k0 + c4);
        }
    };

    auto store_smem = [&](int s) {
        char* st = dynsmem + s * STAGE_B;
        #pragma unroll
        for (int i = 0; i < 8; i++) {
            const int idx = tid + i * 256;
            const int row = idx >> 4;
            const int c4  = idx & 15;
            const uint32_t off = (uint32_t)(row * (RS * 2) + c4 * 8);
            uint32_t h01 = pack_bf16x2(va[i].x, va[i].y);
            uint32_t h23 = pack_bf16x2(va[i].z, va[i].w);
            float lx = va[i].x - __uint_as_float(h01 << 16);
            float ly = va[i].y - __uint_as_float(h01 & 0xffff0000u);
            float lz = va[i].z - __uint_as_float(h23 << 16);
            float lw = va[i].w - __uint_as_float(h23 & 0xffff0000u);
            *(uint2*)(st + OFF_AH + off) = make_uint2(h01, h23);
            *(uint2*)(st + OFF_AL + off) = make_uint2(pack_bf16x2(lx, ly), pack_bf16x2(lz, lw));
        }
        #pragma unroll
        for (int i = 0; i < 4; i++) {
            const int idx = tid + i * 256;
            const int row = idx >> 4;
            const int c4  = idx & 15;
            const uint32_t off = (uint32_t)(row * (RS * 2) + c4 * 8);
            uint32_t h01 = pack_bf16x2(vb[i].x, vb[i].y);
            uint32_t h23 = pack_bf16x2(vb[i].z, vb[i].w);
            float lx = vb[i].x - __uint_as_float(h01 << 16);
            float ly = vb[i].y - __uint_as_float(h01 & 0xffff0000u);
            float lz = vb[i].z - __uint_as_float(h23 << 16);
            float lw = vb[i].w - __uint_as_float(h23 & 0xffff0000u);
            *(uint2*)(st + OFF_BH + off) = make_uint2(h01, h23);
            *(uint2*)(st + OFF_BL + off) = make_uint2(pack_bf16x2(lx, ly), pack_bf16x2(lz, lw));
        }
    };

    auto compute = [&](int s) {
        const uint32_t st = sbase + (uint32_t)(s * STAGE_B);
        #pragma unroll
        for (int ks = 0; ks < 4; ks++) {
            const uint32_t kb = (uint32_t)(ks * 16 * 2);
            uint32_t ah[2][4], al[2][4], bh[4][2], bl[4][2];
            #pragma unroll
            for (int mi = 0; mi < 2; mi++) {
                const uint32_t ra = st + (uint32_t)((wm * 32 + mi * 16 + a_row) * (RS * 2))
                                   + kb + (uint32_t)(a_kof * 2);
                ldsm_x4(ah[mi], ra + OFF_AH);
                ldsm_x4(al[mi], ra + OFF_AL);
            }
            #pragma unroll
            for (int bi = 0; bi < 2; bi++) {
                const uint32_t rb = st + (uint32_t)((wn * 32 + bi * 16 + b_row) * (RS * 2))
                                   + kb + (uint32_t)(b_kof * 2);
                uint32_t t0[4], t1[4];
                ldsm_x4(t0, rb + OFF_BH);
                ldsm_x4(t1, rb + OFF_BL);
                bh[bi*2+0][0] = t0[0]; bh[bi*2+0][1] = t0[1];
                bh[bi*2+1][0] = t0[2]; bh[bi*2+1][1] = t0[3];
                bl[bi*2+0][0] = t1[0]; bl[bi*2+0][1] = t1[1];
                bl[bi*2+1][0] = t1[2]; bl[bi*2+1][1] = t1[3];
            }
            #pragma unroll
            for (int mi = 0; mi < 2; mi++)
                #pragma unroll
                for (int nf = 0; nf < 4; nf++) {
                    mma_bf16(acc[mi][nf], ah[mi], bh[nf]);
                    mma_bf16(acc[mi][nf], ah[mi], bl[nf]);
                    mma_bf16(acc[mi][nf], al[mi], bh[nf]);
                }
        }
    };

    load_regs(0);
    store_smem(0);
    __syncthreads();

    for (int ch = 0; ch < 16; ch++) {
        const int s = ch & 1;
        if (ch < 15) load_regs(ch + 1);
        compute(s);
        if (ch < 15) store_smem(s ^ 1);
        __syncthreads();
    }

    // -------- Epilogue: stage 128x64 fp32 tile in smem (stride 65) --------
    float* ep = (float*)dynsmem;
    #pragma unroll
    for (int mi = 0; mi < 2; mi++)
        #pragma unroll
        for (int nf = 0; nf < 4; nf++)
            #pragma unroll
            for (int j = 0; j < 4; j++) {
                const int r = wm * 32 + mi * 16 + (lane >> 2) + (j >> 1) * 8;
                const int c = wn * 32 + nf * 8 + (lane & 3) * 2 + (j & 1);
                ep[r * 65 + c] = acc[mi][nf][j];
            }
    __syncthreads();

    if (z == 0) {
        // g_qph[bq][a/2]: pairs over n (a) within a row; coalesced over c2.
        #pragma unroll
        for (int i = 0; i < 16; i++) {
            const int idx = tid + i * 256;    // 0..4095
            const int row = idx >> 5;         // 0..127
            const int c2  = idx & 31;         // 0..31
            __half2 h = __floats2half2_rn(ep[row * 65 + 2 * c2],
                                          ep[row * 65 + 2 * c2 + 1]);
            g_qph[(size_t)(m0 + row) * (NA / 2) + (n0 >> 1) + c2] = h;
        }
    } else {
        // g_kph[a/2][bt]: pairs over n (a); coalesced over m.
        #pragma unroll
        for (int i = 0; i < 16; i++) {
            const int idx = tid + i * 256;    // 0..4095
            const int c2  = idx >> 7;         // 0..31
            const int m   = idx & 127;        // 0..127
            __half2 h = __floats2half2_rn(ep[m * 65 + 2 * c2],
                                          ep[m * 65 + 2 * c2 + 1]);
            g_kph[(size_t)((n0 >> 1) + c2) * (NB * NTK) + m0 + m] = h;
        }
    }
}

// ---------------------------------------------------------------------------
// Fused score + masked softmax, v4: persistent 148 CTAs, half2 tanh.
// CTA = 512 threads = 2 a-halves x 256 t. Items = (b, q) rows, strided grid.
// score = sum_a w3[a] * tanh(qp[q][a] + kp[t][a]) via tanh.approx.f16x2,
// widened to fp32 and accumulated with fp32 w3.
// ---------------------------------------------------------------------------
__global__ __launch_bounds__(512, 1) void score_kernel(
    const int* __restrict__ mask, const float* __restrict__ w3,
    float* __restrict__ out)
{
    __shared__ __align__(16) __half2 qp_sh[NA / 2];   // 256 half2 = full row
    __shared__ float w3_s[NA];
    __shared__ float part[NTK];
    __shared__ float redm[8];
    __shared__ float reds[8];

    const int tid = threadIdx.x;
    const int t   = tid & 255;              // key index
    const int ah  = tid >> 8;               // a-half 0/1

    w3_s[tid] = w3[tid];                    // 512 threads -> full w3

    const int nItems = NB * NTQ;            // 1024 (b,q) rows

    for (int item = blockIdx.x; item < nItems; item += GRID_SCORE) {
        const int b = item >> 8;

        // stage qp row (ah0 threads); barrier also orders part[] reuse.
        if (tid < 256) qp_sh[tid] = g_qph[(size_t)item * (NA / 2) + tid];
        __syncthreads();

        const __half2* kcol = g_kph + (size_t)(ah * 128) * (NB * NTK)
                              + (size_t)b * NTK + t;

        float acc = 0.f;

        __half2 kv[8], kvn[8];
        #pragma unroll
        for (int j = 0; j < 8; j++)
            kv[j] = __ldg(kcol + (size_t)j * (NB * NTK));

        #pragma unroll 4
        for (int it = 0; it < 16; it++) {
            if (it < 15) {
                const __half2* kn = kcol + (size_t)((it + 1) * 8) * (NB * NTK);
                #pragma unroll
                for (int j = 0; j < 8; j++)
                    kvn[j] = __ldg(kn + (size_t)j * (NB * NTK));
            }
            const int base = ah * 128 + it * 8;          // half2 index
            #pragma unroll
            for (int j4 = 0; j4 < 2; j4++) {
                uint4 uq = ((const uint4*)qp_sh)[(base >> 2) + j4];
                uint32_t uu[4] = {uq.x, uq.y, uq.z, uq.w};
                float4 wA = *(const float4*)&w3_s[2 * base + 8 * j4];
                float4 wB = *(const float4*)&w3_s[2 * base + 8 * j4 + 4];
                #pragma unroll
                for (int e = 0; e < 4; e++) {
                    __half2 qh = *(__half2*)&uu[e];
                    __half2 th = tanh_h2(__hadd2(qh, kv[j4 * 4 + e]));
                    const float wlo = e < 2 ? (&wA.x)[e * 2]     : (&wB.x)[(e - 2) * 2];
                    const float whi = e < 2 ? (&wA.x)[e * 2 + 1] : (&wB.x)[(e - 2) * 2 + 1];
                    acc = fmaf(wlo, __low2float(th),  acc);
                    acc = fmaf(whi, __high2float(th), acc);
                }
            }
            #pragma unroll
            for (int j = 0; j < 8; j++) kv[j] = kvn[j];
        }

        // combine a-halves
        if (ah == 1) part[t] = acc;
        __syncthreads();

        float sc = 0.f, ex = 0.f;
        const int lane = t & 31, warp = t >> 5;

        if (ah == 0) {
            acc += part[t];
            const int mv = mask[(size_t)item * NTK + t];
            sc = mv ? acc : -1e10f;
            float v = sc;
            #pragma unroll
            for (int o = 16; o; o >>= 1) v = fmaxf(v, __shfl_xor_sync(0xffffffffu, v, o));
            if (lane == 0) redm[warp] = v;
        }
        __syncthreads();

        if (ah == 0) {
            float m = redm[0];
            #pragma unroll
            for (int w = 1; w < 8; w++) m = fmaxf(m, redm[w]);
            ex = exp2f((sc - m) * 1.4426950408889634f);
            float v = ex;
            #pragma unroll
            for (int o = 16; o; o >>= 1) v += __shfl_xor_sync(0xffffffffu, v, o);
            if (lane == 0) reds[warp] = v;
        }
        __syncthreads();

        if (ah == 0) {
            float s = reds[0];
            #pragma unroll
            for (int w = 1; w < 8; w++) s += reds[w];
            out[(size_t)item * NTK + t] = ex * __frcp_rn(s);
        }
    }
}

// ---------------------------------------------------------------------------
extern "C" void kernel_launch(void* const* d_in, const int* in_sizes, int n_in,
                              void* d_out, int out_size)
{
    const float* Q    = (const float*)d_in[0];
    const float* K    = (const float*)d_in[1];
    const int*   mask = (const int*)d_in[2];
    const float* W1   = (const float*)d_in[3];
    const float* W2   = (const float*)d_in[4];
    const float* w3   = (const float*)d_in[5];
    float*       out  = (float*)d_out;

    cudaFuncSetAttribute(proj_tc_kernel,
                         cudaFuncAttributeMaxDynamicSharedMemorySize, SMEM_DYN);

    dim3 gp(NA / BN, (NB * NTQ) / BM, 2);   // 8 x 8 x 2 = 128 CTAs
    proj_tc_kernel<<<gp, 256, SMEM_DYN>>>(Q, K, W1, W2);

    score_kernel<<<GRID_SCORE, 512>>>(mask, w3, out);
}

// round 9
// speedup vs baseline: 1.0287x; 1.0287x over previous
#include <cuda_runtime.h>
#include <cuda_bf16.h>
#include <cuda_fp16.h>
#include <cstdint>
#include <cstddef>

// Problem constants
#define NB   4
#define NTQ  256
#define NTK  256
#define ND   1024
#define NA   512

#define GRID_SCORE 296     // persistent: 2 CTAs per SM

// Scratch (allocation-free rule: __device__ globals).
__device__ __half2 g_qph[NB * NTQ * (NA / 2)];     // [b*TQ+q][a/2]
__device__ uint4   g_kp4[(NA / 8) * NB * NTK];     // [a/8][b*TK+t] : 4x half2

// ---------------------------------------------------------------------------
// Helpers
// ---------------------------------------------------------------------------
__device__ __forceinline__ uint32_t cvta_shared_u32(const void* p) {
    uint32_t a;
    asm("{ .reg .u64 t; cvta.to.shared.u64 t, %1; cvt.u32.u64 %0, t; }"
        : "=r"(a) : "l"(p));
    return a;
}

// Pack two floats into bf16x2 (a -> low 16 bits, b -> high).
__device__ __forceinline__ uint32_t pack_bf16x2(float a, float b) {
    uint32_t r;
    asm("cvt.rn.bf16x2.f32 %0, %1, %2;" : "=r"(r) : "f"(b), "f"(a));
    return r;
}

__device__ __forceinline__ void ldsm_x4(uint32_t* r, uint32_t addr) {
    asm volatile("ldmatrix.sync.aligned.m8n8.x4.shared.b16 {%0,%1,%2,%3}, [%4];"
                 : "=r"(r[0]), "=r"(r[1]), "=r"(r[2]), "=r"(r[3]) : "r"(addr));
}

__device__ __forceinline__ void mma_bf16(float* c, const uint32_t* a, const uint32_t* b) {
    asm volatile(
        "mma.sync.aligned.m16n8k16.row.col.f32.bf16.bf16.f32 "
        "{%0,%1,%2,%3}, {%4,%5,%6,%7}, {%8,%9}, {%0,%1,%2,%3};"
        : "+f"(c[0]), "+f"(c[1]), "+f"(c[2]), "+f"(c[3])
        : "r"(a[0]), "r"(a[1]), "r"(a[2]), "r"(a[3]), "r"(b[0]), "r"(b[1]));
}

__device__ __forceinline__ __half2 tanh_h2(__half2 x) {
    uint32_t xi = *(uint32_t*)&x, r;
    asm("tanh.approx.f16x2 %0, %1;" : "=r"(r) : "r"(xi));
    return *(__half2*)&r;
}

// ---------------------------------------------------------------------------
// Tensor-core projection GEMM via mma.sync bf16 hi/lo split (3-MMA fp32 emu).
// z=0: Q*W1 -> g_qph (row-major, half2-packed over a).
// z=1: K*W2 -> g_kp4 ([a/8][bt] uint4-packed groups of 8 a's).
// ---------------------------------------------------------------------------
#define BM 128
#define BN 64
#define BK 64
#define RS 72                    // smem row stride in bf16 (144 B)
#define A_TILE_B  (BM * RS * 2)  // 18432
#define B_TILE_B  (BN * RS * 2)  //  9216
#define STAGE_B   (2 * A_TILE_B + 2 * B_TILE_B)   // Ah, Al, Bh, Bl = 55296
#define OFF_AH 0
#define OFF_AL A_TILE_B
#define OFF_BH (2 * A_TILE_B)
#define OFF_BL (2 * A_TILE_B + B_TILE_B)
#define SMEM_DYN (2 * STAGE_B)   // 110592

extern __shared__ char dynsmem[];

__global__ __launch_bounds__(256, 1) void proj_tc_kernel(
    const float* __restrict__ Qin, const float* __restrict__ Kin,
    const float* __restrict__ W1,  const float* __restrict__ W2)
{
    const int z  = blockIdx.z;
    const float* X = z ? Kin : Qin;
    const float* W = z ? W2  : W1;
    const int m0 = blockIdx.y * BM;
    const int n0 = blockIdx.x * BN;

    const int tid  = threadIdx.x;
    const int wid  = tid >> 5;
    const int lane = tid & 31;
    const int wm   = wid >> 1;        // 0..3
    const int wn   = wid & 1;         // 0..1

    const uint32_t sbase = cvta_shared_u32(dynsmem);

    const int a_row = (lane & 7) + ((lane >> 3) & 1) * 8;   // 0..15
    const int a_kof = (lane >> 4) * 8;                      // 0 / 8
    const int b_row = (lane & 7) + ((lane >> 4) & 1) * 8;
    const int b_kof = ((lane >> 3) & 1) * 8;

    float acc[2][4][4] = {};   // [mi][nf][4]

    float4 va[8], vb[4];

    auto load_regs = [&](int ch) {
        const int k0 = ch * BK;
        #pragma unroll
        for (int i = 0; i < 8; i++) {
            const int idx = tid + i * 256;
            const int row = idx >> 4;
            const int c4  = (idx & 15) * 4;
            va[i] = *(const float4*)(X + (size_t)(m0 + row) * ND + k0 + c4);
        }
        #pragma unroll
        for (int i = 0; i < 4; i++) {
            const int idx = tid + i * 256;
            const int row = idx >> 4;
            const int c4  = (idx & 15) * 4;
            vb[i] = *(const float4*)(W + (size_t)(n0 + row) * ND + k0 + c4);
        }
    };

    auto store_smem = [&](int s) {
        char* st = dynsmem + s * STAGE_B;
        #pragma unroll
        for (int i = 0; i < 8; i++) {
            const int idx = tid + i * 256;
            const int row = idx >> 4;
            const int c4  = idx & 15;
            const uint32_t off = (uint32_t)(row * (RS * 2) + c4 * 8);
            uint32_t h01 = pack_bf16x2(va[i].x, va[i].y);
            uint32_t h23 = pack_bf16x2(va[i].z, va[i].w);
            float lx = va[i].x - __uint_as_float(h01 << 16);
            float ly = va[i].y - __uint_as_float(h01 & 0xffff0000u);
            float lz = va[i].z - __uint_as_float(h23 << 16);
            float lw = va[i].w - __uint_as_float(h23 & 0xffff0000u);
            *(uint2*)(st + OFF_AH + off) = make_uint2(h01, h23);
            *(uint2*)(st + OFF_AL + off) = make_uint2(pack_bf16x2(lx, ly), pack_bf16x2(lz, lw));
        }
        #pragma unroll
        for (int i = 0; i < 4; i++) {
            const int idx = tid + i * 256;
            const int row = idx >> 4;
            const int c4  = idx & 15;
            const uint32_t off = (uint32_t)(row * (RS * 2) + c4 * 8);
            uint32_t h01 = pack_bf16x2(vb[i].x, vb[i].y);
            uint32_t h23 = pack_bf16x2(vb[i].z, vb[i].w);
            float lx = vb[i].x - __uint_as_float(h01 << 16);
            float ly = vb[i].y - __uint_as_float(h01 & 0xffff0000u);
            float lz = vb[i].z - __uint_as_float(h23 << 16);
            float lw = vb[i].w - __uint_as_float(h23 & 0xffff0000u);
            *(uint2*)(st + OFF_BH + off) = make_uint2(h01, h23);
            *(uint2*)(st + OFF_BL + off) = make_uint2(pack_bf16x2(lx, ly), pack_bf16x2(lz, lw));
        }
    };

    auto compute = [&](int s) {
        const uint32_t st = sbase + (uint32_t)(s * STAGE_B);
        #pragma unroll
        for (int ks = 0; ks < 4; ks++) {
            const uint32_t kb = (uint32_t)(ks * 16 * 2);
            uint32_t ah[2][4], al[2][4], bh[4][2], bl[4][2];
            #pragma unroll
            for (int mi = 0; mi < 2; mi++) {
                const uint32_t ra = st + (uint32_t)((wm * 32 + mi * 16 + a_row) * (RS * 2))
                                   + kb + (uint32_t)(a_kof * 2);
                ldsm_x4(ah[mi], ra + OFF_AH);
                ldsm_x4(al[mi], ra + OFF_AL);
            }
            #pragma unroll
            for (int bi = 0; bi < 2; bi++) {
                const uint32_t rb = st + (uint32_t)((wn * 32 + bi * 16 + b_row) * (RS * 2))
                                   + kb + (uint32_t)(b_kof * 2);
                uint32_t t0[4], t1[4];
                ldsm_x4(t0, rb + OFF_BH);
                ldsm_x4(t1, rb + OFF_BL);
                bh[bi*2+0][0] = t0[0]; bh[bi*2+0][1] = t0[1];
                bh[bi*2+1][0] = t0[2]; bh[bi*2+1][1] = t0[3];
                bl[bi*2+0][0] = t1[0]; bl[bi*2+0][1] = t1[1];
                bl[bi*2+1][0] = t1[2]; bl[bi*2+1][1] = t1[3];
            }
            #pragma unroll
            for (int mi = 0; mi < 2; mi++)
                #pragma unroll
                for (int nf = 0; nf < 4; nf++) {
                    mma_bf16(acc[mi][nf], ah[mi], bh[nf]);
                    mma_bf16(acc[mi][nf], ah[mi], bl[nf]);
                    mma_bf16(acc[mi][nf], al[mi], bh[nf]);
                }
        }
    };

    load_regs(0);
    store_smem(0);
    __syncthreads();

    for (int ch = 0; ch < 16; ch++) {
        const int s = ch & 1;
        if (ch < 15) load_regs(ch + 1);
        compute(s);
        if (ch < 15) store_smem(s ^ 1);
        __syncthreads();
    }

    // -------- Epilogue: stage 128x64 fp32 tile in smem (stride 65) --------
    float* ep = (float*)dynsmem;
    #pragma unroll
    for (int mi = 0; mi < 2; mi++)
        #pragma unroll
        for (int nf = 0; nf < 4; nf++)
            #pragma unroll
            for (int j = 0; j < 4; j++) {
                const int r = wm * 32 + mi * 16 + (lane >> 2) + (j >> 1) * 8;
                const int c = wn * 32 + nf * 8 + (lane & 3) * 2 + (j & 1);
                ep[r * 65 + c] = acc[mi][nf][j];
            }
    __syncthreads();

    if (z == 0) {
        // g_qph[bq][a/2]
        #pragma unroll
        for (int i = 0; i < 16; i++) {
            const int idx = tid + i * 256;    // 0..4095
            const int row = idx >> 5;         // 0..127
            const int c2  = idx & 31;         // 0..31
            __half2 h = __floats2half2_rn(ep[row * 65 + 2 * c2],
                                          ep[row * 65 + 2 * c2 + 1]);
            g_qph[(size_t)(m0 + row) * (NA / 2) + (n0 >> 1) + c2] = h;
        }
    } else {
        // g_kp4[a/8][bt]: uint4 of 4 half2 covering 8 consecutive a's.
        #pragma unroll
        for (int i = 0; i < 4; i++) {
            const int idx = tid + i * 256;    // 0..1023
            const int m   = idx & 127;        // 0..127
            const int gg  = idx >> 7;         // 0..7
            const float* row = &ep[m * 65 + 8 * gg];
            __half2 h0 = __floats2half2_rn(row[0], row[1]);
            __half2 h1 = __floats2half2_rn(row[2], row[3]);
            __half2 h2 = __floats2half2_rn(row[4], row[5]);
            __half2 h3 = __floats2half2_rn(row[6], row[7]);
            uint4 v;
            v.x = *(uint32_t*)&h0; v.y = *(uint32_t*)&h1;
            v.z = *(uint32_t*)&h2; v.w = *(uint32_t*)&h3;
            g_kp4[(size_t)((n0 >> 3) + gg) * (NB * NTK) + m0 + m] = v;
        }
    }
}

// ---------------------------------------------------------------------------
// Fused score + masked softmax, v5: persistent 296 CTAs (2/SM), half2 tanh,
// HFMA2 accumulation (two alternating half2 accs, fp32 flush per 16 terms),
// uint4-vectorized kp loads.
// ---------------------------------------------------------------------------
__global__ __launch_bounds__(512, 2) void score_kernel(
    const int* __restrict__ mask, const float* __restrict__ w3,
    float* __restrict__ out)
{
    __shared__ __align__(16) uint4 qp4[NA / 8];   // 64 x (8 a's)
    __shared__ __align__(16) uint4 w34[NA / 8];
    __shared__ float part[NTK];
    __shared__ float redm[8];
    __shared__ float reds[8];

    const int tid = threadIdx.x;
    const int t   = tid & 255;              // key index
    const int ah  = tid >> 8;               // a-half 0/1

    if (tid < 256)
        ((__half2*)w34)[tid] = __floats2half2_rn(w3[2 * tid], w3[2 * tid + 1]);

    const int nItems = NB * NTQ;            // 1024 (b,q) rows

    for (int item = blockIdx.x; item < nItems; item += GRID_SCORE) {
        const int b = item >> 8;

        if (tid < 64) qp4[tid] = ((const uint4*)g_qph)[item * 64 + tid];
        __syncthreads();

        const uint4* gk4 = g_kp4 + (size_t)(ah * 32) * (NB * NTK)
                           + (size_t)b * NTK + t;

        uint4 kc0 = __ldg(gk4);
        uint4 kc1 = __ldg(gk4 + (NB * NTK));
        float acc = 0.f;

        #pragma unroll 2
        for (int it = 0; it < 16; it++) {
            uint4 kn0, kn1;
            if (it < 15) {
                kn0 = __ldg(gk4 + (size_t)(2 * it + 2) * (NB * NTK));
                kn1 = __ldg(gk4 + (size_t)(2 * it + 3) * (NB * NTK));
            }
            const int base = ah * 32 + 2 * it;

            __half2 accA = __floats2half2_rn(0.f, 0.f);
            __half2 accB = accA;

            auto step = [&](const uint4& uq, const uint4& uw, const uint4& kv) {
                const uint32_t* q = (const uint32_t*)&uq;
                const uint32_t* w = (const uint32_t*)&uw;
                const uint32_t* k = (const uint32_t*)&kv;
                #pragma unroll
                for (int e = 0; e < 4; e++) {
                    __half2 th = tanh_h2(__hadd2(*(__half2*)&q[e], *(__half2*)&k[e]));
                    if (e & 1) accB = __hfma2(*(__half2*)&w[e], th, accB);
                    else       accA = __hfma2(*(__half2*)&w[e], th, accA);
                }
            };
            step(qp4[base],     w34[base],     kc0);
            step(qp4[base + 1], w34[base + 1], kc1);

            acc += __low2float(accA) + __high2float(accA)
                 + __low2float(accB) + __high2float(accB);

            if (it < 15) { kc0 = kn0; kc1 = kn1; }
        }

        // combine a-halves
        if (ah == 1) part[t] = acc;
        __syncthreads();

        float sc = 0.f, ex = 0.f;
        const int lane = t & 31, warp = t >> 5;

        if (ah == 0) {
            acc += part[t];
            const int mv = mask[(size_t)item * NTK + t];
            sc = mv ? acc : -1e10f;
            float v = sc;
            #pragma unroll
            for (int o = 16; o; o >>= 1) v = fmaxf(v, __shfl_xor_sync(0xffffffffu, v, o));
            if (lane == 0) redm[warp] = v;
        }
        __syncthreads();

        if (ah == 0) {
            float m = redm[0];
            #pragma unroll
            for (int w = 1; w < 8; w++) m = fmaxf(m, redm[w]);
            ex = exp2f((sc - m) * 1.4426950408889634f);
            float v = ex;
            #pragma unroll
            for (int o = 16; o; o >>= 1) v += __shfl_xor_sync(0xffffffffu, v, o);
            if (lane == 0) reds[warp] = v;
        }
        __syncthreads();

        if (ah == 0) {
            float s = reds[0];
            #pragma unroll
            for (int w = 1; w < 8; w++) s += reds[w];
            out[(size_t)item * NTK + t] = ex * __frcp_rn(s);
        }
    }
}

// ---------------------------------------------------------------------------
extern "C" void kernel_launch(void* const* d_in, const int* in_sizes, int n_in,
                              void* d_out, int out_size)
{
    const float* Q    = (const float*)d_in[0];
    const float* K    = (const float*)d_in[1];
    const int*   mask = (const int*)d_in[2];
    const float* W1   = (const float*)d_in[3];
    const float* W2   = (const float*)d_in[4];
    const float* w3   = (const float*)d_in[5];
    float*       out  = (float*)d_out;

    cudaFuncSetAttribute(proj_tc_kernel,
                         cudaFuncAttributeMaxDynamicSharedMemorySize, SMEM_DYN);

    dim3 gp(NA / BN, (NB * NTQ) / BM, 2);   // 8 x 8 x 2 = 128 CTAs
    proj_tc_kernel<<<gp, 256, SMEM_DYN>>>(Q, K, W1, W2);

    score_kernel<<<GRID_SCORE, 512>>>(mask, w3, out);
}

// round 10
// speedup vs baseline: 1.0882x; 1.0579x over previous
#include <cuda_runtime.h>
#include <cuda_bf16.h>
#include <cuda_fp16.h>
#include <cstdint>
#include <cstddef>

// Problem constants
#define NB   4
#define NTQ  256
#define NTK  256
#define ND   1024
#define NA   512

// Scratch (allocation-free rule: __device__ globals).
__device__ __half2 g_qph[NB * NTQ * (NA / 2)];     // [b*TQ+q][a/2]
__device__ uint4   g_kp4[(NA / 8) * NB * NTK];     // [a/8][b*TK+t] : 4x half2

// ---------------------------------------------------------------------------
// Helpers
// ---------------------------------------------------------------------------
__device__ __forceinline__ uint32_t cvta_shared_u32(const void* p) {
    uint32_t a;
    asm("{ .reg .u64 t; cvta.to.shared.u64 t, %1; cvt.u32.u64 %0, t; }"
        : "=r"(a) : "l"(p));
    return a;
}

// Pack two floats into bf16x2 (a -> low 16 bits, b -> high).
__device__ __forceinline__ uint32_t pack_bf16x2(float a, float b) {
    uint32_t r;
    asm("cvt.rn.bf16x2.f32 %0, %1, %2;" : "=r"(r) : "f"(b), "f"(a));
    return r;
}

__device__ __forceinline__ void ldsm_x4(uint32_t* r, uint32_t addr) {
    asm volatile("ldmatrix.sync.aligned.m8n8.x4.shared.b16 {%0,%1,%2,%3}, [%4];"
                 : "=r"(r[0]), "=r"(r[1]), "=r"(r[2]), "=r"(r[3]) : "r"(addr));
}

__device__ __forceinline__ void mma_bf16(float* c, const uint32_t* a, const uint32_t* b) {
    asm volatile(
        "mma.sync.aligned.m16n8k16.row.col.f32.bf16.bf16.f32 "
        "{%0,%1,%2,%3}, {%4,%5,%6,%7}, {%8,%9}, {%0,%1,%2,%3};"
        : "+f"(c[0]), "+f"(c[1]), "+f"(c[2]), "+f"(c[3])
        : "r"(a[0]), "r"(a[1]), "r"(a[2]), "r"(a[3]), "r"(b[0]), "r"(b[1]));
}

__device__ __forceinline__ __half2 tanh_h2(__half2 x) {
    uint32_t xi = *(uint32_t*)&x, r;
    asm("tanh.approx.f16x2 %0, %1;" : "=r"(r) : "r"(xi));
    return *(__half2*)&r;
}

// ---------------------------------------------------------------------------
// Tensor-core projection GEMM via mma.sync bf16 hi/lo split (3-MMA fp32 emu).
// z=0: Q*W1 -> g_qph (row-major, half2-packed over a).
// z=1: K*W2 -> g_kp4 ([a/8][bt] uint4-packed groups of 8 a's).
// ---------------------------------------------------------------------------
#define BM 128
#define BN 64
#define BK 64
#define RS 72                    // smem row stride in bf16 (144 B)
#define A_TILE_B  (BM * RS * 2)  // 18432
#define B_TILE_B  (BN * RS * 2)  //  9216
#define STAGE_B   (2 * A_TILE_B + 2 * B_TILE_B)   // Ah, Al, Bh, Bl = 55296
#define OFF_AH 0
#define OFF_AL A_TILE_B
#define OFF_BH (2 * A_TILE_B)
#define OFF_BL (2 * A_TILE_B + B_TILE_B)
#define SMEM_DYN (2 * STAGE_B)   // 110592

extern __shared__ char dynsmem[];

__global__ __launch_bounds__(256, 1) void proj_tc_kernel(
    const float* __restrict__ Qin, const float* __restrict__ Kin,
    const float* __restrict__ W1,  const float* __restrict__ W2)
{
    const int z  = blockIdx.z;
    const float* X = z ? Kin : Qin;
    const float* W = z ? W2  : W1;
    const int m0 = blockIdx.y * BM;
    const int n0 = blockIdx.x * BN;

    const int tid  = threadIdx.x;
    const int wid  = tid >> 5;
    const int lane = tid & 31;
    const int wm   = wid >> 1;        // 0..3
    const int wn   = wid & 1;         // 0..1

    const uint32_t sbase = cvta_shared_u32(dynsmem);

    const int a_row = (lane & 7) + ((lane >> 3) & 1) * 8;   // 0..15
    const int a_kof = (lane >> 4) * 8;                      // 0 / 8
    const int b_row = (lane & 7) + ((lane >> 4) & 1) * 8;
    const int b_kof = ((lane >> 3) & 1) * 8;

    float acc[2][4][4] = {};   // [mi][nf][4]

    float4 va[8], vb[4];

    auto load_regs = [&](int ch) {
        const int k0 = ch * BK;
        #pragma unroll
        for (int i = 0; i < 8; i++) {
            const int idx = tid + i * 256;
            const int row = idx >> 4;
            const int c4  = (idx & 15) * 4;
            va[i] = *(const float4*)(X + (size_t)(m0 + row) * ND + k0 + c4);
        }
        #pragma unroll
        for (int i = 0; i < 4; i++) {
            const int idx = tid + i * 256;
            const int row = idx >> 4;
            const int c4  = (idx & 15) * 4;
            vb[i] = *(const float4*)(W + (size_t)(n0 + row) * ND + k0 + c4);
        }
    };

    auto store_smem = [&](int s) {
        char* st = dynsmem + s * STAGE_B;
        #pragma unroll
        for (int i = 0; i < 8; i++) {
            const int idx = tid + i * 256;
            const int row = idx >> 4;
            const int c4  = idx & 15;
            const uint32_t off = (uint32_t)(row * (RS * 2) + c4 * 8);
            uint32_t h01 = pack_bf16x2(va[i].x, va[i].y);
            uint32_t h23 = pack_bf16x2(va[i].z, va[i].w);
            float lx = va[i].x - __uint_as_float(h01 << 16);
            float ly = va[i].y - __uint_as_float(h01 & 0xffff0000u);
            float lz = va[i].z - __uint_as_float(h23 << 16);
            float lw = va[i].w - __uint_as_float(h23 & 0xffff0000u);
            *(uint2*)(st + OFF_AH + off) = make_uint2(h01, h23);
            *(uint2*)(st + OFF_AL + off) = make_uint2(pack_bf16x2(lx, ly), pack_bf16x2(lz, lw));
        }
        #pragma unroll
        for (int i = 0; i < 4; i++) {
            const int idx = tid + i * 256;
            const int row = idx >> 4;
            const int c4  = idx & 15;
            const uint32_t off = (uint32_t)(row * (RS * 2) + c4 * 8);
            uint32_t h01 = pack_bf16x2(vb[i].x, vb[i].y);
            uint32_t h23 = pack_bf16x2(vb[i].z, vb[i].w);
            float lx = vb[i].x - __uint_as_float(h01 << 16);
            float ly = vb[i].y - __uint_as_float(h01 & 0xffff0000u);
            float lz = vb[i].z - __uint_as_float(h23 << 16);
            float lw = vb[i].w - __uint_as_float(h23 & 0xffff0000u);
            *(uint2*)(st + OFF_BH + off) = make_uint2(h01, h23);
            *(uint2*)(st + OFF_BL + off) = make_uint2(pack_bf16x2(lx, ly), pack_bf16x2(lz, lw));
        }
    };

    auto compute = [&](int s) {
        const uint32_t st = sbase + (uint32_t)(s * STAGE_B);
        #pragma unroll
        for (int ks = 0; ks < 4; ks++) {
            const uint32_t kb = (uint32_t)(ks * 16 * 2);
            uint32_t ah[2][4], al[2][4], bh[4][2], bl[4][2];
            #pragma unroll
            for (int mi = 0; mi < 2; mi++) {
                const uint32_t ra = st + (uint32_t)((wm * 32 + mi * 16 + a_row) * (RS * 2))
                                   + kb + (uint32_t)(a_kof * 2);
                ldsm_x4(ah[mi], ra + OFF_AH);
                ldsm_x4(al[mi], ra + OFF_AL);
            }
            #pragma unroll
            for (int bi = 0; bi < 2; bi++) {
                const uint32_t rb = st + (uint32_t)((wn * 32 + bi * 16 + b_row) * (RS * 2))
                                   + kb + (uint32_t)(b_kof * 2);
                uint32_t t0[4], t1[4];
                ldsm_x4(t0, rb + OFF_BH);
                ldsm_x4(t1, rb + OFF_BL);
                bh[bi*2+0][0] = t0[0]; bh[bi*2+0][1] = t0[1];
                bh[bi*2+1][0] = t0[2]; bh[bi*2+1][1] = t0[3];
                bl[bi*2+0][0] = t1[0]; bl[bi*2+0][1] = t1[1];
                bl[bi*2+1][0] = t1[2]; bl[bi*2+1][1] = t1[3];
            }
            #pragma unroll
            for (int mi = 0; mi < 2; mi++)
                #pragma unroll
                for (int nf = 0; nf < 4; nf++) {
                    mma_bf16(acc[mi][nf], ah[mi], bh[nf]);
                    mma_bf16(acc[mi][nf], ah[mi], bl[nf]);
                    mma_bf16(acc[mi][nf], al[mi], bh[nf]);
                }
        }
    };

    load_regs(0);
    store_smem(0);
    __syncthreads();

    for (int ch = 0; ch < 16; ch++) {
        const int s = ch & 1;
        if (ch < 15) load_regs(ch + 1);
        compute(s);
        if (ch < 15) store_smem(s ^ 1);
        __syncthreads();
    }

    // -------- Epilogue: stage 128x64 fp32 tile in smem (stride 65) --------
    float* ep = (float*)dynsmem;
    #pragma unroll
    for (int mi = 0; mi < 2; mi++)
        #pragma unroll
        for (int nf = 0; nf < 4; nf++)
            #pragma unroll
            for (int j = 0; j < 4; j++) {
                const int r = wm * 32 + mi * 16 + (lane >> 2) + (j >> 1) * 8;
                const int c = wn * 32 + nf * 8 + (lane & 3) * 2 + (j & 1);
                ep[r * 65 + c] = acc[mi][nf][j];
            }
    __syncthreads();

    if (z == 0) {
        // g_qph[bq][a/2]
        #pragma unroll
        for (int i = 0; i < 16; i++) {
            const int idx = tid + i * 256;    // 0..4095
            const int row = idx >> 5;         // 0..127
            const int c2  = idx & 31;         // 0..31
            __half2 h = __floats2half2_rn(ep[row * 65 + 2 * c2],
                                          ep[row * 65 + 2 * c2 + 1]);
            g_qph[(size_t)(m0 + row) * (NA / 2) + (n0 >> 1) + c2] = h;
        }
    } else {
        // g_kp4[a/8][bt]: uint4 of 4 half2 covering 8 consecutive a's.
        #pragma unroll
        for (int i = 0; i < 4; i++) {
            const int idx = tid + i * 256;    // 0..1023
            const int m   = idx & 127;        // 0..127
            const int gg  = idx >> 7;         // 0..7
            const float* row = &ep[m * 65 + 8 * gg];
            __half2 h0 = __floats2half2_rn(row[0], row[1]);
            __half2 h1 = __floats2half2_rn(row[2], row[3]);
            __half2 h2 = __floats2half2_rn(row[4], row[5]);
            __half2 h3 = __floats2half2_rn(row[6], row[7]);
            uint4 v;
            v.x = *(uint32_t*)&h0; v.y = *(uint32_t*)&h1;
            v.z = *(uint32_t*)&h2; v.w = *(uint32_t*)&h3;
            g_kp4[(size_t)((n0 >> 3) + gg) * (NB * NTK) + m0 + m] = v;
        }
    }
}

// ---------------------------------------------------------------------------
// Fused score + masked softmax, v6.
// CTA = (b, 4 q rows); grid 256 = one wave at 2 CTAs/SM.
// 512 threads = 2 a-halves x 256 t. Each kv load feeds 4 q rows -> per-element
// issue overhead amortized 4x; loop is MUFU-bound (32 MUFU vs ~140 slots/iter
// against a 256-cycle MUFU pipe time).
// ---------------------------------------------------------------------------
__global__ __launch_bounds__(512, 2) void score_kernel(
    const int* __restrict__ mask, const float* __restrict__ w3,
    float* __restrict__ out)
{
    __shared__ __align__(16) uint4 qp4s[4][NA / 8];   // [q][64]
    __shared__ __align__(16) uint4 w34[NA / 8];
    __shared__ float part[4][NTK];
    __shared__ float redm[4][8];
    __shared__ float reds[4][8];

    const int tid  = threadIdx.x;
    const int t    = tid & 255;             // key index
    const int ah   = tid >> 8;              // a-half 0/1
    const int item = blockIdx.x;            // 0..255
    const int b    = item >> 6;
    const int q0   = (item & 63) * 4;

    if (tid < 256) {
        ((__half2*)w34)[tid] = __floats2half2_rn(w3[2 * tid], w3[2 * tid + 1]);
        const int q = tid >> 6, g = tid & 63;
        qp4s[q][g] = ((const uint4*)g_qph)[(size_t)(b * NTQ + q0 + q) * 64 + g];
    }
    __syncthreads();

    const uint4* gk4 = g_kp4 + (size_t)(ah * 32) * (NB * NTK)
                       + (size_t)b * NTK + t;

    float acc[4] = {0.f, 0.f, 0.f, 0.f};

    uint4 kc0 = __ldg(gk4);
    uint4 kc1 = __ldg(gk4 + (NB * NTK));

    #pragma unroll 2
    for (int it = 0; it < 16; it++) {
        uint4 kn0, kn1;
        if (it < 15) {
            kn0 = __ldg(gk4 + (size_t)(2 * it + 2) * (NB * NTK));
            kn1 = __ldg(gk4 + (size_t)(2 * it + 3) * (NB * NTK));
        }
        const int base = ah * 32 + 2 * it;
        uint4 uw0 = w34[base], uw1 = w34[base + 1];
        const uint32_t* w0 = (const uint32_t*)&uw0;
        const uint32_t* w1 = (const uint32_t*)&uw1;
        const uint32_t* k0 = (const uint32_t*)&kc0;
        const uint32_t* k1 = (const uint32_t*)&kc1;

        #pragma unroll
        for (int q = 0; q < 4; q++) {
            uint4 uq0 = qp4s[q][base], uq1 = qp4s[q][base + 1];
            const uint32_t* qa = (const uint32_t*)&uq0;
            const uint32_t* qb = (const uint32_t*)&uq1;
            __half2 acA = __floats2half2_rn(0.f, 0.f);
            __half2 acB = acA;
            #pragma unroll
            for (int e = 0; e < 4; e++) {
                __half2 th = tanh_h2(__hadd2(*(__half2*)&qa[e], *(__half2*)&k0[e]));
                if (e & 1) acB = __hfma2(*(__half2*)&w0[e], th, acB);
                else       acA = __hfma2(*(__half2*)&w0[e], th, acA);
            }
            #pragma unroll
            for (int e = 0; e < 4; e++) {
                __half2 th = tanh_h2(__hadd2(*(__half2*)&qb[e], *(__half2*)&k1[e]));
                if (e & 1) acB = __hfma2(*(__half2*)&w1[e], th, acB);
                else       acA = __hfma2(*(__half2*)&w1[e], th, acA);
            }
            __half2 hs = __hadd2(acA, acB);
            acc[q] += __low2float(hs) + __high2float(hs);
        }
        if (it < 15) { kc0 = kn0; kc1 = kn1; }
    }

    // combine a-halves
    if (ah == 1) {
        #pragma unroll
        for (int q = 0; q < 4; q++) part[q][t] = acc[q];
    }
    __syncthreads();

    float sc[4], ex[4];
    const int lane = t & 31, warp = t >> 5;

    if (ah == 0) {
        #pragma unroll
        for (int q = 0; q < 4; q++) {
            acc[q] += part[q][t];
            const int mv = mask[((size_t)b * NTQ + q0 + q) * NTK + t];
            sc[q] = mv ? acc[q] : -1e10f;
            float v = sc[q];
            #pragma unroll
            for (int o = 16; o; o >>= 1) v = fmaxf(v, __shfl_xor_sync(0xffffffffu, v, o));
            if (lane == 0) redm[q][warp] = v;
        }
    }
    __syncthreads();

    if (ah == 0) {
        #pragma unroll
        for (int q = 0; q < 4; q++) {
            float m = redm[q][0];
            #pragma unroll
            for (int w = 1; w < 8; w++) m = fmaxf(m, redm[q][w]);
            ex[q] = exp2f((sc[q] - m) * 1.4426950408889634f);
            float v = ex[q];
            #pragma unroll
            for (int o = 16; o; o >>= 1) v += __shfl_xor_sync(0xffffffffu, v, o);
            if (lane == 0) reds[q][warp] = v;
        }
    }
    __syncthreads();

    if (ah == 0) {
        #pragma unroll
        for (int q = 0; q < 4; q++) {
            float s = reds[q][0];
            #pragma unroll
            for (int w = 1; w < 8; w++) s += reds[q][w];
            out[((size_t)b * NTQ + q0 + q) * NTK + t] = ex[q] * __frcp_rn(s);
        }
    }
}

// ---------------------------------------------------------------------------
extern "C" void kernel_launch(void* const* d_in, const int* in_sizes, int n_in,
                              void* d_out, int out_size)
{
    const float* Q    = (const float*)d_in[0];
    const float* K    = (const float*)d_in[1];
    const int*   mask = (const int*)d_in[2];
    const float* W1   = (const float*)d_in[3];
    const float* W2   = (const float*)d_in[4];
    const float* w3   = (const float*)d_in[5];
    float*       out  = (float*)d_out;

    cudaFuncSetAttribute(proj_tc_kernel,
                         cudaFuncAttributeMaxDynamicSharedMemorySize, SMEM_DYN);

    dim3 gp(NA / BN, (NB * NTQ) / BM, 2);   // 8 x 8 x 2 = 128 CTAs
    proj_tc_kernel<<<gp, 256, SMEM_DYN>>>(Q, K, W1, W2);

    score_kernel<<<NB * NTQ / 4, 512>>>(mask, w3, out);   // 256 CTAs, one wave
}

// round 11
// speedup vs baseline: 1.4754x; 1.3558x over previous
#include <cuda_runtime.h>
#include <cuda_fp16.h>
#include <cstdint>
#include <cstddef>

// Problem constants
#define NB   4
#define NTQ  256
#define NTK  256
#define ND   1024
#define NA   512

// Scratch (allocation-free rule: __device__ globals).
__device__ __half2 g_qph[NB * NTQ * (NA / 2)];     // [b*TQ+q][a/2]
__device__ uint4   g_kp4[(NA / 8) * NB * NTK];     // [a/8][b*TK+t] : 4x half2

// ---------------------------------------------------------------------------
// Helpers
// ---------------------------------------------------------------------------
__device__ __forceinline__ uint32_t cvta_shared_u32(const void* p) {
    uint32_t a;
    asm("{ .reg .u64 t; cvta.to.shared.u64 t, %1; cvt.u32.u64 %0, t; }"
        : "=r"(a) : "l"(p));
    return a;
}

__device__ __forceinline__ void ldsm_x4(uint32_t* r, uint32_t addr) {
    asm volatile("ldmatrix.sync.aligned.m8n8.x4.shared.b16 {%0,%1,%2,%3}, [%4];"
                 : "=r"(r[0]), "=r"(r[1]), "=r"(r[2]), "=r"(r[3]) : "r"(addr));
}

__device__ __forceinline__ void mma_f16(float* c, const uint32_t* a, const uint32_t* b) {
    asm volatile(
        "mma.sync.aligned.m16n8k16.row.col.f32.f16.f16.f32 "
        "{%0,%1,%2,%3}, {%4,%5,%6,%7}, {%8,%9}, {%0,%1,%2,%3};"
        : "+f"(c[0]), "+f"(c[1]), "+f"(c[2]), "+f"(c[3])
        : "r"(a[0]), "r"(a[1]), "r"(a[2]), "r"(a[3]), "r"(b[0]), "r"(b[1]));
}

__device__ __forceinline__ __half2 tanh_h2(__half2 x) {
    uint32_t xi = *(uint32_t*)&x, r;
    asm("tanh.approx.f16x2 %0, %1;" : "=r"(r) : "r"(xi));
    return *(__half2*)&r;
}

__device__ __forceinline__ uint32_t h2bits(__half2 h) { return *(uint32_t*)&h; }

// ---------------------------------------------------------------------------
// Tensor-core projection GEMM via mma.sync fp16 hi/lo split (2-MMA emu):
//   D = Ah*Bh + Al*Bh   (drops Ah*Bl ~2.8e-4 rel, under error budget)
// z=0: Q*W1 -> g_qph (row-major, half2-packed over a).
// z=1: K*W2 -> g_kp4 ([a/8][bt] uint4-packed groups of 8 a's).
// ---------------------------------------------------------------------------
#define BM 128
#define BN 64
#define BK 64
#define RS 72                    // smem row stride in fp16 (144 B)
#define A_TILE_B  (BM * RS * 2)  // 18432
#define B_TILE_B  (BN * RS * 2)  //  9216
#define STAGE_B   (2 * A_TILE_B + B_TILE_B)   // Ah, Al, Bh = 46080
#define OFF_AH 0
#define OFF_AL A_TILE_B
#define OFF_BH (2 * A_TILE_B)
#define SMEM_DYN (2 * STAGE_B)   // 92160

extern __shared__ char dynsmem[];

__global__ __launch_bounds__(256, 1) void proj_tc_kernel(
    const float* __restrict__ Qin, const float* __restrict__ Kin,
    const float* __restrict__ W1,  const float* __restrict__ W2)
{
    const int z  = blockIdx.z;
    const float* X = z ? Kin : Qin;
    const float* W = z ? W2  : W1;
    const int m0 = blockIdx.y * BM;
    const int n0 = blockIdx.x * BN;

    const int tid  = threadIdx.x;
    const int wid  = tid >> 5;
    const int lane = tid & 31;
    const int wm   = wid >> 1;        // 0..3
    const int wn   = wid & 1;         // 0..1

    const uint32_t sbase = cvta_shared_u32(dynsmem);

    const int a_row = (lane & 7) + ((lane >> 3) & 1) * 8;   // 0..15
    const int a_kof = (lane >> 4) * 8;                      // 0 / 8
    const int b_row = (lane & 7) + ((lane >> 4) & 1) * 8;
    const int b_kof = ((lane >> 3) & 1) * 8;

    float acc[2][4][4] = {};   // [mi][nf][4]

    float4 va[8], vb[4];

    auto load_regs = [&](int ch) {
        const int k0 = ch * BK;
        #pragma unroll
        for (int i = 0; i < 8; i++) {
            const int idx = tid + i * 256;
            const int row = idx >> 4;
            const int c4  = (idx & 15) * 4;
            va[i] = *(const float4*)(X + (size_t)(m0 + row) * ND + k0 + c4);
        }
        #pragma unroll
        for (int i = 0; i < 4; i++) {
            const int idx = tid + i * 256;
            const int row = idx >> 4;
            const int c4  = (idx & 15) * 4;
            vb[i] = *(const float4*)(W + (size_t)(n0 + row) * ND + k0 + c4);
        }
    };

    auto store_smem = [&](int s) {
        char* st = dynsmem + s * STAGE_B;
        #pragma unroll
        for (int i = 0; i < 8; i++) {
            const int idx = tid + i * 256;
            const int row = idx >> 4;
            const int c4  = idx & 15;
            const uint32_t off = (uint32_t)(row * (RS * 2) + c4 * 8);
            __half2 h01 = __floats2half2_rn(va[i].x, va[i].y);
            __half2 h23 = __floats2half2_rn(va[i].z, va[i].w);
            float lx = va[i].x - __half2float(__low2half(h01));
            float ly = va[i].y - __half2float(__high2half(h01));
            float lz = va[i].z - __half2float(__low2half(h23));
            float lw = va[i].w - __half2float(__high2half(h23));
            *(uint2*)(st + OFF_AH + off) = make_uint2(h2bits(h01), h2bits(h23));
            *(uint2*)(st + OFF_AL + off) =
                make_uint2(h2bits(__floats2half2_rn(lx, ly)),
                           h2bits(__floats2half2_rn(lz, lw)));
        }
        #pragma unroll
        for (int i = 0; i < 4; i++) {
            const int idx = tid + i * 256;
            const int row = idx >> 4;
            const int c4  = idx & 15;
            const uint32_t off = (uint32_t)(row * (RS * 2) + c4 * 8);
            __half2 h01 = __floats2half2_rn(vb[i].x, vb[i].y);
            __half2 h23 = __floats2half2_rn(vb[i].z, vb[i].w);
            *(uint2*)(st + OFF_BH + off) = make_uint2(h2bits(h01), h2bits(h23));
        }
    };

    auto compute = [&](int s) {
        const uint32_t st = sbase + (uint32_t)(s * STAGE_B);
        #pragma unroll
        for (int ks = 0; ks < 4; ks++) {
            const uint32_t kb = (uint32_t)(ks * 16 * 2);
            uint32_t ah[2][4], al[2][4], bh[4][2];
            #pragma unroll
            for (int mi = 0; mi < 2; mi++) {
                const uint32_t ra = st + (uint32_t)((wm * 32 + mi * 16 + a_row) * (RS * 2))
                                   + kb + (uint32_t)(a_kof * 2);
                ldsm_x4(ah[mi], ra + OFF_AH);
                ldsm_x4(al[mi], ra + OFF_AL);
            }
            #pragma unroll
            for (int bi = 0; bi < 2; bi++) {
                const uint32_t rb = st + (uint32_t)((wn * 32 + bi * 16 + b_row) * (RS * 2))
                                   + kb + (uint32_t)(b_kof * 2);
                uint32_t t0[4];
                ldsm_x4(t0, rb + OFF_BH);
                bh[bi*2+0][0] = t0[0]; bh[bi*2+0][1] = t0[1];
                bh[bi*2+1][0] = t0[2]; bh[bi*2+1][1] = t0[3];
            }
            #pragma unroll
            for (int mi = 0; mi < 2; mi++)
                #pragma unroll
                for (int nf = 0; nf < 4; nf++) {
                    mma_f16(acc[mi][nf], ah[mi], bh[nf]);
                    mma_f16(acc[mi][nf], al[mi], bh[nf]);
                }
        }
    };

    load_regs(0);
    store_smem(0);
    __syncthreads();

    for (int ch = 0; ch < 16; ch++) {
        const int s = ch & 1;
        if (ch < 15) load_regs(ch + 1);
        compute(s);
        if (ch < 15) store_smem(s ^ 1);
        __syncthreads();
    }

    // -------- Epilogue: stage 128x64 fp32 tile in smem (stride 65) --------
    float* ep = (float*)dynsmem;
    #pragma unroll
    for (int mi = 0; mi < 2; mi++)
        #pragma unroll
        for (int nf = 0; nf < 4; nf++)
            #pragma unroll
            for (int j = 0; j < 4; j++) {
                const int r = wm * 32 + mi * 16 + (lane >> 2) + (j >> 1) * 8;
                const int c = wn * 32 + nf * 8 + (lane & 3) * 2 + (j & 1);
                ep[r * 65 + c] = acc[mi][nf][j];
            }
    __syncthreads();

    if (z == 0) {
        #pragma unroll
        for (int i = 0; i < 16; i++) {
            const int idx = tid + i * 256;    // 0..4095
            const int row = idx >> 5;         // 0..127
            const int c2  = idx & 31;         // 0..31
            __half2 h = __floats2half2_rn(ep[row * 65 + 2 * c2],
                                          ep[row * 65 + 2 * c2 + 1]);
            g_qph[(size_t)(m0 + row) * (NA / 2) + (n0 >> 1) + c2] = h;
        }
    } else {
        #pragma unroll
        for (int i = 0; i < 4; i++) {
            const int idx = tid + i * 256;    // 0..1023
            const int m   = idx & 127;        // 0..127
            const int gg  = idx >> 7;         // 0..7
            const float* row = &ep[m * 65 + 8 * gg];
            __half2 h0 = __floats2half2_rn(row[0], row[1]);
            __half2 h1 = __floats2half2_rn(row[2], row[3]);
            __half2 h2 = __floats2half2_rn(row[4], row[5]);
            __half2 h3 = __floats2half2_rn(row[6], row[7]);
            uint4 v;
            v.x = h2bits(h0); v.y = h2bits(h1);
            v.z = h2bits(h2); v.w = h2bits(h3);
            g_kp4[(size_t)((n0 >> 3) + gg) * (NB * NTK) + m0 + m] = v;
        }
    }
}

// ---------------------------------------------------------------------------
// Fused score + masked softmax, v7: mask compaction.
// CTA = (b, 4 q rows), 512 threads, grid 256 (one wave at 2 CTAs/SM).
// Active (q,t) pairs (~50% of 1024) are compacted; each thread computes the
// full 512-a score for ~1 active pair. Scores scatter into an smem tile
// pre-set to -1e10; softmax then runs unchanged over t in [0,256).
// ---------------------------------------------------------------------------
#define KSTRIDE (NB * NTK)      // uint4 elements between a-groups

__global__ __launch_bounds__(512, 2) void score_kernel(
    const int* __restrict__ mask, const float* __restrict__ w3,
    float* __restrict__ out)
{
    __shared__ __align__(16) uint4 qp4s[4][NA / 8];   // [q][64]
    __shared__ __align__(16) uint4 w34[NA / 8];
    __shared__ float sc_s[4][NTK];
    __shared__ short idx_s[4][NTK];
    __shared__ int   wcnt[4][8], wbase[4][8], qoff[5];
    __shared__ float redm[4][8], reds[4][8];

    const int tid  = threadIdx.x;
    const int t2   = tid & 255;
    const int wh   = tid >> 8;              // 0: q{0,1}, 1: q{2,3}
    const int wrp  = (tid >> 5) & 7;
    const int lane = tid & 31;
    const int item = blockIdx.x;            // 0..255
    const int b    = item >> 6;
    const int q0   = (item & 63) * 4;

    // stage qp rows + w3 (first 256 threads)
    if (tid < 256) {
        ((__half2*)w34)[tid] = __floats2half2_rn(w3[2 * tid], w3[2 * tid + 1]);
        const int q = tid >> 6, g = tid & 63;
        qp4s[q][g] = ((const uint4*)g_qph)[(size_t)(b * NTQ + q0 + q) * 64 + g];
    }

    // ---- mask ballot-compaction: warps 0-7 handle q0,q1; 8-15 handle q2,q3
    const int qa = 2 * wh, qb = 2 * wh + 1;
    const int mva = mask[((size_t)b * NTQ + q0 + qa) * NTK + t2];
    const int mvb = mask[((size_t)b * NTQ + q0 + qb) * NTK + t2];
    const unsigned bala = __ballot_sync(0xffffffffu, mva != 0);
    const unsigned balb = __ballot_sync(0xffffffffu, mvb != 0);
    if (lane == 0) { wcnt[qa][wrp] = __popc(bala); wcnt[qb][wrp] = __popc(balb); }
    const int posa = __popc(bala & ((1u << lane) - 1));
    const int posb = __popc(balb & ((1u << lane) - 1));

    // init score tile to -1e10 (1024 entries, 2 per thread)
    ((float*)sc_s)[tid]       = -1e10f;
    ((float*)sc_s)[tid + 512] = -1e10f;
    __syncthreads();

    if (tid == 0) {
        int s = 0;
        #pragma unroll
        for (int q = 0; q < 4; q++) {
            qoff[q] = s;
            #pragma unroll
            for (int w = 0; w < 8; w++) { wbase[q][w] = s; s += wcnt[q][w]; }
        }
        qoff[4] = s;
    }
    __syncthreads();

    if (mva) idx_s[qa][wbase[qa][wrp] - qoff[qa] + posa] = (short)t2;
    if (mvb) idx_s[qb][wbase[qb][wrp] - qoff[qb] + posb] = (short)t2;
    __syncthreads();

    const int total = qoff[4];
    const int o1 = qoff[1], o2 = qoff[2], o3 = qoff[3];

    for (int i = tid; i < total; i += 512) {
        const int q  = (i >= o1) + (i >= o2) + (i >= o3);
        const int t  = idx_s[q][i - qoff[q]];
        const uint4* gk = g_kp4 + (size_t)b * NTK + t;

        float acc = 0.f;
        uint4 kc0 = __ldg(gk);
        uint4 kc1 = __ldg(gk + KSTRIDE);

        #pragma unroll 4
        for (int g = 0; g < 32; g++) {
            uint4 kn0, kn1;
            if (g < 31) {
                kn0 = __ldg(gk + (size_t)(2 * g + 2) * KSTRIDE);
                kn1 = __ldg(gk + (size_t)(2 * g + 3) * KSTRIDE);
            }
            uint4 uw0 = w34[2 * g], uw1 = w34[2 * g + 1];
            uint4 uq0 = qp4s[q][2 * g], uq1 = qp4s[q][2 * g + 1];
            const uint32_t* w0 = (const uint32_t*)&uw0;
            const uint32_t* w1 = (const uint32_t*)&uw1;
            const uint32_t* qv0 = (const uint32_t*)&uq0;
            const uint32_t* qv1 = (const uint32_t*)&uq1;
            const uint32_t* k0 = (const uint32_t*)&kc0;
            const uint32_t* k1 = (const uint32_t*)&kc1;

            __half2 acA = __floats2half2_rn(0.f, 0.f);
            __half2 acB = acA;
            #pragma unroll
            for (int e = 0; e < 4; e++) {
                __half2 th = tanh_h2(__hadd2(*(__half2*)&qv0[e], *(__half2*)&k0[e]));
                if (e & 1) acB = __hfma2(*(__half2*)&w0[e], th, acB);
                else       acA = __hfma2(*(__half2*)&w0[e], th, acA);
            }
            #pragma unroll
            for (int e = 0; e < 4; e++) {
                __half2 th = tanh_h2(__hadd2(*(__half2*)&qv1[e], *(__half2*)&k1[e]));
                if (e & 1) acB = __hfma2(*(__half2*)&w1[e], th, acB);
                else       acA = __hfma2(*(__half2*)&w1[e], th, acA);
            }
            __half2 hs = __hadd2(acA, acB);
            acc += __low2float(hs) + __high2float(hs);

            if (g < 31) { kc0 = kn0; kc1 = kn1; }
        }
        sc_s[q][t] = acc;
    }
    __syncthreads();

    // ---- softmax over t (first 256 threads; masked slots hold -1e10)
    float sc[4], ex[4];
    if (tid < 256) {
        #pragma unroll
        for (int q = 0; q < 4; q++) {
            sc[q] = sc_s[q][t2];
            float v = sc[q];
            #pragma unroll
            for (int o = 16; o; o >>= 1) v = fmaxf(v, __shfl_xor_sync(0xffffffffu, v, o));
            if (lane == 0) redm[q][wrp] = v;
        }
    }
    __syncthreads();

    if (tid < 256) {
        #pragma unroll
        for (int q = 0; q < 4; q++) {
            float m = redm[q][0];
            #pragma unroll
            for (int w = 1; w < 8; w++) m = fmaxf(m, redm[q][w]);
            ex[q] = exp2f((sc[q] - m) * 1.4426950408889634f);
            float v = ex[q];
            #pragma unroll
            for (int o = 16; o; o >>= 1) v += __shfl_xor_sync(0xffffffffu, v, o);
            if (lane == 0) reds[q][wrp] = v;
        }
    }
    __syncthreads();

    if (tid < 256) {
        #pragma unroll
        for (int q = 0; q < 4; q++) {
            float s = reds[q][0];
            #pragma unroll
            for (int w = 1; w < 8; w++) s += reds[q][w];
            out[((size_t)b * NTQ + q0 + q) * NTK + t2] = ex[q] * __frcp_rn(s);
        }
    }
}

// ---------------------------------------------------------------------------
extern "C" void kernel_launch(void* const* d_in, const int* in_sizes, int n_in,
                              void* d_out, int out_size)
{
    const float* Q    = (const float*)d_in[0];
    const float* K    = (const float*)d_in[1];
    const int*   mask = (const int*)d_in[2];
    const float* W1   = (const float*)d_in[3];
    const float* W2   = (const float*)d_in[4];
    const float* w3   = (const float*)d_in[5];
    float*       out  = (float*)d_out;

    cudaFuncSetAttribute(proj_tc_kernel,
                         cudaFuncAttributeMaxDynamicSharedMemorySize, SMEM_DYN);

    dim3 gp(NA / BN, (NB * NTQ) / BM, 2);   // 8 x 8 x 2 = 128 CTAs
    proj_tc_kernel<<<gp, 256, SMEM_DYN>>>(Q, K, W1, W2);

    score_kernel<<<NB * NTQ / 4, 512>>>(mask, w3, out);   // 256 CTAs, one wave
}